// round 6
// baseline (speedup 1.0000x reference)
#include <cuda_runtime.h>
#include <math.h>
#include <stdint.h>

#define D    512
#define BLKR 64
#define NB   128        // batch
#define M    6304       // memory contexts
#define TOPK 50
#define CEPS 1e-8f
#define KSPLIT 4

// ---------------- scratch ----------------
__device__ float g_msq[KSPLIT][M];               // partial sum-of-squares of mc rows
__device__ float g_cosp[KSPLIT][(size_t)NB * M]; // partial dot products
__device__ int   g_tidx[NB * TOPK];
__device__ float g_tw[NB * TOPK];

// ---------------- 1) dot = q @ mc^T, packed f32x2 FMA, split-K=4 ----------------
// BM=128, BN=32, BK=32. 128 threads; thread tile 8x4 (rows ty+16i, cols tx+8j).
// Also emits per-row sum-of-squares of mc (for cosine norms) from the B loader.
#define GBN 32
#define GBK 32
#define APAD 36

__device__ __forceinline__ void ffma2(unsigned long long &d,
                                      unsigned long long a,
                                      unsigned long long b) {
    asm("fma.rn.f32x2 %0, %1, %2, %0;" : "+l"(d) : "l"(a), "l"(b));
}

__global__ __launch_bounds__(128) void cos_gemm_kernel(const float* __restrict__ q,
                                                       const float* __restrict__ mc) {
    __shared__ float As[NB][APAD];    // 18 KB
    __shared__ float Bs[GBN][APAD];   // 4.5 KB
    int t  = threadIdx.x;
    int tx = t & 7;                   // cols tx + 8j
    int ty = t >> 3;                  // rows ty + 16i (ty in 0..15)
    int m0 = blockIdx.x * GBN;
    int kz = blockIdx.y;
    int kbase = kz * (D / KSPLIT);

    unsigned long long acc[8][4];
#pragma unroll
    for (int i = 0; i < 8; i++)
#pragma unroll
        for (int j = 0; j < 4; j++) acc[i][j] = 0ull;

    float ss0 = 0.f, ss1 = 0.f;       // sum-of-squares for B rows (t>>3) and (t>>3)+16

    for (int kt = 0; kt < (D / KSPLIT); kt += GBK) {
        int k0 = kbase + kt;
        // A tile: 128x32 floats = 1024 float4, 8 per thread
#pragma unroll
        for (int i = 0; i < 8; i++) {
            int lin = t + i * 128;
            int row = lin >> 3, c4 = lin & 7;
            float4 v = *(const float4*)(q + (size_t)row * D + k0 + c4 * 4);
            *(float4*)&As[row][c4 * 4] = v;
        }
        // B tile: 32x32 floats = 256 float4, 2 per thread; accumulate row ss
#pragma unroll
        for (int i = 0; i < 2; i++) {
            int lin = t + i * 128;
            int row = lin >> 3, c4 = lin & 7;
            float4 v = *(const float4*)(mc + (size_t)(m0 + row) * D + k0 + c4 * 4);
            *(float4*)&Bs[row][c4 * 4] = v;
            float s = v.x * v.x + v.y * v.y + v.z * v.z + v.w * v.w;
            if (i == 0) ss0 += s; else ss1 += s;
        }
        __syncthreads();
#pragma unroll
        for (int k4 = 0; k4 < GBK / 4; k4++) {
            float4 bf[4];
#pragma unroll
            for (int j = 0; j < 4; j++) bf[j] = *(const float4*)&Bs[tx + 8 * j][k4 * 4];
            float4 af[8];
#pragma unroll
            for (int i = 0; i < 8; i++) af[i] = *(const float4*)&As[ty + 16 * i][k4 * 4];
#pragma unroll
            for (int i = 0; i < 8; i++) {
                const unsigned long long* ap = (const unsigned long long*)&af[i];
#pragma unroll
                for (int j = 0; j < 4; j++) {
                    const unsigned long long* bp = (const unsigned long long*)&bf[j];
                    ffma2(acc[i][j], ap[0], bp[0]);
                    ffma2(acc[i][j], ap[1], bp[1]);
                }
            }
        }
        __syncthreads();
    }

    // reduce row ss across the 8 loader lanes (t^1, t^2, t^4 share the same row)
#pragma unroll
    for (int o = 4; o > 0; o >>= 1) {
        ss0 += __shfl_xor_sync(0xffffffffu, ss0, o);
        ss1 += __shfl_xor_sync(0xffffffffu, ss1, o);
    }
    if ((t & 7) == 0) {
        g_msq[kz][m0 + (t >> 3)]      = ss0;
        g_msq[kz][m0 + (t >> 3) + 16] = ss1;
    }

    float* dst = &g_cosp[kz][0];
#pragma unroll
    for (int i = 0; i < 8; i++) {
        int br = ty + 16 * i;
#pragma unroll
        for (int j = 0; j < 4; j++) {
            unsigned long long a = acc[i][j];
            float lo = __uint_as_float((unsigned)(a & 0xffffffffu));
            float hi = __uint_as_float((unsigned)(a >> 32));
            dst[(size_t)br * M + m0 + tx + 8 * j] = lo + hi;
        }
    }
}

// ---------------- 2) radix-select top-50 + softmax (norms fused in) ----------------
#define TIECAP 256

__device__ __forceinline__ unsigned key_of(float v) {
    unsigned u = __float_as_uint(v);
    return (u & 0x80000000u) ? ~u : (u | 0x80000000u);   // monotonic flip
}
__device__ __forceinline__ float val_of(unsigned k) {
    unsigned u = (k & 0x80000000u) ? (k & 0x7fffffffu) : ~k;
    return __uint_as_float(u);
}

__global__ __launch_bounds__(256) void topk_kernel(const float* __restrict__ q) {
    __shared__ unsigned keys[M];            // 25.2 KB
    __shared__ int suf[257];                // suffix counts (suf[256]=0)
    __shared__ unsigned s_prefix;
    __shared__ int s_remaining;
    __shared__ int s_gtcnt, s_tiecnt;
    __shared__ unsigned gt_k[64];
    __shared__ int gt_i[64];
    __shared__ int tie_i[TIECAP];
    __shared__ int fin_idx[TOPK];
    __shared__ float fin_val[TOPK];
    __shared__ float fin_e[TOPK];
    __shared__ float s_sum;
    __shared__ float s_qred[4];
    __shared__ float s_qi;

    int b = blockIdx.x, t = threadIdx.x;

    // q row norm for this batch (t<128 each read one float4)
    {
        float ss = 0.f;
        if (t < 128) {
            float4 v = ((const float4*)(q + (size_t)b * D))[t];
            ss = v.x * v.x + v.y * v.y + v.z * v.z + v.w * v.w;
        }
#pragma unroll
        for (int o = 16; o > 0; o >>= 1) ss += __shfl_xor_sync(0xffffffffu, ss, o);
        if (t < 128 && (t & 31) == 0) s_qred[t >> 5] = ss;
        __syncthreads();
        if (t == 0) {
            float tot = (s_qred[0] + s_qred[1]) + (s_qred[2] + s_qred[3]);
            s_qi = 1.0f / fmaxf(sqrtf(tot), CEPS);
        }
        __syncthreads();
    }
    float qi = s_qi;

    const float* p0 = &g_cosp[0][(size_t)b * M];
    const float* p1 = &g_cosp[1][(size_t)b * M];
    const float* p2 = &g_cosp[2][(size_t)b * M];
    const float* p3 = &g_cosp[3][(size_t)b * M];

    for (int i = t; i < M; i += 256) {
        float tot = (g_msq[0][i] + g_msq[1][i]) + (g_msq[2][i] + g_msq[3][i]);
        float minv = 1.0f / fmaxf(sqrtf(tot), CEPS);
        float v = ((p0[i] + p1[i]) + (p2[i] + p3[i])) * qi * minv;
        keys[i] = key_of(v);
    }
    if (t == 0) { s_prefix = 0u; s_remaining = TOPK; s_gtcnt = 0; s_tiecnt = 0; }
    __syncthreads();

#pragma unroll
    for (int level = 0; level < 4; level++) {
        int shift = 24 - level * 8;
        suf[t] = 0;
        if (t == 0) suf[256] = 0;
        __syncthreads();
        unsigned pfx = s_prefix;
        for (int i = t; i < M; i += 256) {
            unsigned k = keys[i];
            bool in = (level == 0) || ((k >> (shift + 8)) == pfx);
            if (in) atomicAdd(&suf[(k >> shift) & 255], 1);
        }
        __syncthreads();
#pragma unroll
        for (int s = 1; s < 256; s <<= 1) {
            int add = (t + s < 256) ? suf[t + s] : 0;
            __syncthreads();
            suf[t] += add;
            __syncthreads();
        }
        int rem = s_remaining;
        if (suf[t] >= rem && suf[t + 1] < rem) {
            s_prefix = (s_prefix << 8) | (unsigned)t;
            s_remaining = rem - suf[t + 1];
        }
        __syncthreads();
    }

    unsigned T = s_prefix;               // exact 50th-largest key
    int rem = s_remaining;
    for (int i = t; i < M; i += 256) {
        unsigned k = keys[i];
        if (k > T) {
            int p = atomicAdd(&s_gtcnt, 1);
            gt_k[p] = k; gt_i[p] = i;
        } else if (k == T) {
            int p = atomicAdd(&s_tiecnt, 1);
            if (p < TIECAP) tie_i[p] = i;
        }
    }
    __syncthreads();
    int ngt = s_gtcnt;                   // == TOPK - rem
    int ntie = min(s_tiecnt, TIECAP);
    if (t < ngt) {
        unsigned mk = gt_k[t]; int mi = gt_i[t];
        int rank = 0;
        for (int j = 0; j < ngt; j++) {
            unsigned ok = gt_k[j]; int oi = gt_i[j];
            if (ok > mk || (ok == mk && oi < mi)) rank++;
        }
        fin_idx[rank] = mi;
        fin_val[rank] = val_of(mk);
    }
    if (t < ntie) {
        int mi = tie_i[t];
        int rank = 0;
        for (int j = 0; j < ntie; j++) if (tie_i[j] < mi) rank++;
        if (rank < rem) {
            fin_idx[ngt + rank] = mi;
            fin_val[ngt + rank] = val_of(T);
        }
    }
    __syncthreads();
    if (t < TOPK) fin_e[t] = expf(fin_val[t] - fin_val[0]);
    __syncthreads();
    if (t == 0) {
        float s = 0.f;
        for (int kk = 0; kk < TOPK; kk++) s += fin_e[kk];
        s_sum = 1.0f / s;
    }
    __syncthreads();
    if (t < TOPK) {
        g_tidx[b * TOPK + t] = fin_idx[t];
        g_tw[b * TOPK + t]   = fin_e[t] * s_sum;
    }
}

// ---------------- 3) weighted block gather + blend (l-major, MLP batched) ----
__global__ __launch_bounds__(128) void gather_kernel(const float* __restrict__ enc,
                                                     const float* __restrict__ fp,
                                                     const float* __restrict__ weight,
                                                     float* __restrict__ out) {
    __shared__ const float4* s_p[TOPK];
    __shared__ float s_w[TOPK];
    int b = blockIdx.x & (NB - 1);     // fast dim: batch -> concurrent CTAs share l
    int l = blockIdx.x >> 7;           // slow dim: row within block
    int t = threadIdx.x;               // 128 threads x float4 = 512 floats
    if (t < TOPK) {
        s_p[t] = (const float4*)(fp + ((size_t)g_tidx[b * TOPK + t] * BLKR + l) * D);
        s_w[t] = g_tw[b * TOPK + t];
    }
    __syncthreads();

    float ax = 0.f, ay = 0.f, az = 0.f, aw = 0.f;
#pragma unroll
    for (int kk = 0; kk < TOPK; kk += 10) {
        float4 v[10];
#pragma unroll
        for (int u = 0; u < 10; u++) v[u] = s_p[kk + u][t];
#pragma unroll
        for (int u = 0; u < 10; u++) {
            float w = s_w[kk + u];
            ax += w * v[u].x; ay += w * v[u].y; az += w * v[u].z; aw += w * v[u].w;
        }
    }

    float wm = weight[0];
    float em = 1.f - wm;
    size_t off = ((size_t)b * BLKR + l) * D;
    float4 e = ((const float4*)(enc + off))[t];
    float4 o;
    o.x = ax * wm + e.x * em;
    o.y = ay * wm + e.y * em;
    o.z = az * wm + e.z * em;
    o.w = aw * wm + e.w * em;
    ((float4*)(out + off))[t] = o;
}

// ---------------- launch ----------------
extern "C" void kernel_launch(void* const* d_in, const int* in_sizes, int n_in,
                              void* d_out, int out_size) {
    const float* enc = (const float*)d_in[0];   // [128, 64, 512]
    const float* q   = (const float*)d_in[1];   // [128, 512]
    const float* mc  = (const float*)d_in[2];   // [6304, 512]
    const float* fp  = (const float*)d_in[3];   // [403456, 512]
    const float* w   = (const float*)d_in[4];   // [1]
    float* out = (float*)d_out;                 // [128, 64, 512]

    cos_gemm_kernel<<<dim3(M / GBN, KSPLIT), 128>>>(q, mc);
    topk_kernel<<<NB, 256>>>(q);
    gather_kernel<<<NB * BLKR, 128>>>(enc, fp, w, out);
}

// round 7
// speedup vs baseline: 1.0106x; 1.0106x over previous
#include <cuda_runtime.h>
#include <math.h>
#include <stdint.h>

#define D    512
#define BLKR 64
#define NB   128        // batch
#define M    6304       // memory contexts
#define TOPK 50
#define CEPS 1e-8f
#define KSPLIT 4

// ---------------- scratch ----------------
__device__ float g_msq[KSPLIT][M];               // partial sum-of-squares of mc rows
__device__ float g_cosp[KSPLIT][(size_t)NB * M]; // partial dot products
__device__ int   g_tidx[NB * TOPK];
__device__ float g_tw[NB * TOPK];

// ---------------- 1) dot = q @ mc^T, packed f32x2 FMA, split-K=4 ----------------
// BM=128, BN=32, BK=32. 256 threads; 4x4 thread tile (rows ty+32i, cols tx+8j).
// Double-buffered smem with register prefetch. Emits mc row sum-of-squares.
#define GBN 32
#define GBK 32
#define APAD 36
#define NTILES ((D / KSPLIT) / GBK)   // 4

__device__ __forceinline__ void ffma2(unsigned long long &d,
                                      unsigned long long a,
                                      unsigned long long b) {
    asm("fma.rn.f32x2 %0, %1, %2, %0;" : "+l"(d) : "l"(a), "l"(b));
}

__global__ __launch_bounds__(256, 2) void cos_gemm_kernel(const float* __restrict__ q,
                                                          const float* __restrict__ mc) {
    __shared__ float As[2][NB][APAD];    // 36 KB
    __shared__ float Bs[2][GBN][APAD];   // 9 KB
    int t  = threadIdx.x;
    int tx = t & 7;                   // cols tx + 8j
    int ty = t >> 3;                  // rows ty + 32i (ty in 0..31)
    int m0 = blockIdx.x * GBN;
    int kz = blockIdx.y;
    int kbase = kz * (D / KSPLIT);

    int arow = t >> 3, ac4 = t & 7;   // this thread's A-load coords (4 rows: +64 apart... lin based)
    int brow = t >> 3, bc4 = t & 7;   // B-load coords (1 float4)

    unsigned long long acc[4][4];
#pragma unroll
    for (int i = 0; i < 4; i++)
#pragma unroll
        for (int j = 0; j < 4; j++) acc[i][j] = 0ull;

    float ss = 0.f;                   // sum-of-squares partial for row brow

    float4 pa[4];
    float4 pb;

    // prologue: load tile 0
#pragma unroll
    for (int i = 0; i < 4; i++) {
        int lin = t + i * 256;
        int row = lin >> 3, c4 = lin & 7;
        pa[i] = *(const float4*)(q + (size_t)row * D + kbase + c4 * 4);
    }
    pb = *(const float4*)(mc + (size_t)(m0 + brow) * D + kbase + bc4 * 4);
#pragma unroll
    for (int i = 0; i < 4; i++) {
        int lin = t + i * 256;
        int row = lin >> 3, c4 = lin & 7;
        *(float4*)&As[0][row][c4 * 4] = pa[i];
    }
    *(float4*)&Bs[0][brow][bc4 * 4] = pb;
    ss += pb.x * pb.x + pb.y * pb.y + pb.z * pb.z + pb.w * pb.w;
    __syncthreads();

#pragma unroll
    for (int kt = 0; kt < NTILES; kt++) {
        int buf = kt & 1;
        if (kt + 1 < NTILES) {
            int k0 = kbase + (kt + 1) * GBK;
#pragma unroll
            for (int i = 0; i < 4; i++) {
                int lin = t + i * 256;
                int row = lin >> 3, c4 = lin & 7;
                pa[i] = *(const float4*)(q + (size_t)row * D + k0 + c4 * 4);
            }
            pb = *(const float4*)(mc + (size_t)(m0 + brow) * D + k0 + bc4 * 4);
        }
        // compute current tile
#pragma unroll
        for (int k4 = 0; k4 < GBK / 4; k4++) {
            float4 bf[4];
#pragma unroll
            for (int j = 0; j < 4; j++) bf[j] = *(const float4*)&Bs[buf][tx + 8 * j][k4 * 4];
            float4 af[4];
#pragma unroll
            for (int i = 0; i < 4; i++) af[i] = *(const float4*)&As[buf][ty + 32 * i][k4 * 4];
#pragma unroll
            for (int i = 0; i < 4; i++) {
                const unsigned long long* ap = (const unsigned long long*)&af[i];
#pragma unroll
                for (int j = 0; j < 4; j++) {
                    const unsigned long long* bp = (const unsigned long long*)&bf[j];
                    ffma2(acc[i][j], ap[0], bp[0]);
                    ffma2(acc[i][j], ap[1], bp[1]);
                }
            }
        }
        if (kt + 1 < NTILES) {
            int nb = buf ^ 1;
#pragma unroll
            for (int i = 0; i < 4; i++) {
                int lin = t + i * 256;
                int row = lin >> 3, c4 = lin & 7;
                *(float4*)&As[nb][row][c4 * 4] = pa[i];
            }
            *(float4*)&Bs[nb][brow][bc4 * 4] = pb;
            ss += pb.x * pb.x + pb.y * pb.y + pb.z * pb.z + pb.w * pb.w;
            __syncthreads();
        }
    }

    // reduce ss across the 8 lanes sharing row brow (lanes differ in bc4 = t&7)
#pragma unroll
    for (int o = 4; o > 0; o >>= 1) ss += __shfl_xor_sync(0xffffffffu, ss, o);
    if (bc4 == 0) g_msq[kz][m0 + brow] = ss;

    float* dst = &g_cosp[kz][0];
#pragma unroll
    for (int i = 0; i < 4; i++) {
        int br = ty + 32 * i;
#pragma unroll
        for (int j = 0; j < 4; j++) {
            unsigned long long a = acc[i][j];
            float lo = __uint_as_float((unsigned)(a & 0xffffffffu));
            float hi = __uint_as_float((unsigned)(a >> 32));
            dst[(size_t)br * M + m0 + tx + 8 * j] = lo + hi;
        }
    }
}

// ---------------- 2) radix-select top-50 + softmax (norms fused in) ----------------
#define TIECAP 256

__device__ __forceinline__ unsigned key_of(float v) {
    unsigned u = __float_as_uint(v);
    return (u & 0x80000000u) ? ~u : (u | 0x80000000u);   // monotonic flip
}
__device__ __forceinline__ float val_of(unsigned k) {
    unsigned u = (k & 0x80000000u) ? (k & 0x7fffffffu) : ~k;
    return __uint_as_float(u);
}

__global__ __launch_bounds__(256) void topk_kernel(const float* __restrict__ q) {
    __shared__ unsigned keys[M];            // 25.2 KB
    __shared__ int suf[257];                // suffix counts (suf[256]=0)
    __shared__ unsigned s_prefix;
    __shared__ int s_remaining;
    __shared__ int s_gtcnt, s_tiecnt;
    __shared__ unsigned gt_k[64];
    __shared__ int gt_i[64];
    __shared__ int tie_i[TIECAP];
    __shared__ int fin_idx[TOPK];
    __shared__ float fin_val[TOPK];
    __shared__ float fin_e[TOPK];
    __shared__ float s_sum;
    __shared__ float s_qred[4];
    __shared__ float s_qi;

    int b = blockIdx.x, t = threadIdx.x;

    // q row norm for this batch
    {
        float ssq = 0.f;
        if (t < 128) {
            float4 v = ((const float4*)(q + (size_t)b * D))[t];
            ssq = v.x * v.x + v.y * v.y + v.z * v.z + v.w * v.w;
        }
#pragma unroll
        for (int o = 16; o > 0; o >>= 1) ssq += __shfl_xor_sync(0xffffffffu, ssq, o);
        if (t < 128 && (t & 31) == 0) s_qred[t >> 5] = ssq;
        __syncthreads();
        if (t == 0) {
            float tot = (s_qred[0] + s_qred[1]) + (s_qred[2] + s_qred[3]);
            s_qi = 1.0f / fmaxf(sqrtf(tot), CEPS);
        }
        __syncthreads();
    }
    float qi = s_qi;

    const float* p0 = &g_cosp[0][(size_t)b * M];
    const float* p1 = &g_cosp[1][(size_t)b * M];
    const float* p2 = &g_cosp[2][(size_t)b * M];
    const float* p3 = &g_cosp[3][(size_t)b * M];

    for (int i = t; i < M; i += 256) {
        float tot = (g_msq[0][i] + g_msq[1][i]) + (g_msq[2][i] + g_msq[3][i]);
        float minv = 1.0f / fmaxf(sqrtf(tot), CEPS);
        float v = ((p0[i] + p1[i]) + (p2[i] + p3[i])) * qi * minv;
        keys[i] = key_of(v);
    }
    if (t == 0) { s_prefix = 0u; s_remaining = TOPK; s_gtcnt = 0; s_tiecnt = 0; }
    __syncthreads();

#pragma unroll
    for (int level = 0; level < 4; level++) {
        int shift = 24 - level * 8;
        suf[t] = 0;
        if (t == 0) suf[256] = 0;
        __syncthreads();
        unsigned pfx = s_prefix;
        for (int i = t; i < M; i += 256) {
            unsigned k = keys[i];
            bool in = (level == 0) || ((k >> (shift + 8)) == pfx);
            if (in) atomicAdd(&suf[(k >> shift) & 255], 1);
        }
        __syncthreads();
        // warp 0: suffix scan of 256 bins (8 bins/lane + shfl suffix over lanes)
        if (t < 32) {
            int loc[8];
            int run = 0;
#pragma unroll
            for (int j = 7; j >= 0; j--) { run += suf[t * 8 + j]; loc[j] = run; }
            int x = run;   // chunk sum
#pragma unroll
            for (int o = 1; o < 32; o <<= 1) {
                int y = __shfl_down_sync(0xffffffffu, x, o);
                if (t + o < 32) x += y;
            }
            int excl = x - run;   // sum of chunks above this one
#pragma unroll
            for (int j = 0; j < 8; j++) suf[t * 8 + j] = loc[j] + excl;
        }
        __syncthreads();
        int rem = s_remaining;
        if (suf[t] >= rem && suf[t + 1] < rem) {
            s_prefix = (s_prefix << 8) | (unsigned)t;
            s_remaining = rem - suf[t + 1];
        }
        __syncthreads();
    }

    unsigned T = s_prefix;               // exact 50th-largest key
    int rem = s_remaining;
    for (int i = t; i < M; i += 256) {
        unsigned k = keys[i];
        if (k > T) {
            int p = atomicAdd(&s_gtcnt, 1);
            gt_k[p] = k; gt_i[p] = i;
        } else if (k == T) {
            int p = atomicAdd(&s_tiecnt, 1);
            if (p < TIECAP) tie_i[p] = i;
        }
    }
    __syncthreads();
    int ngt = s_gtcnt;                   // == TOPK - rem
    int ntie = min(s_tiecnt, TIECAP);
    if (t < ngt) {
        unsigned mk = gt_k[t]; int mi = gt_i[t];
        int rank = 0;
        for (int j = 0; j < ngt; j++) {
            unsigned ok = gt_k[j]; int oi = gt_i[j];
            if (ok > mk || (ok == mk && oi < mi)) rank++;
        }
        fin_idx[rank] = mi;
        fin_val[rank] = val_of(mk);
    }
    if (t < ntie) {
        int mi = tie_i[t];
        int rank = 0;
        for (int j = 0; j < ntie; j++) if (tie_i[j] < mi) rank++;
        if (rank < rem) {
            fin_idx[ngt + rank] = mi;
            fin_val[ngt + rank] = val_of(T);
        }
    }
    __syncthreads();
    if (t < TOPK) fin_e[t] = expf(fin_val[t] - fin_val[0]);
    __syncthreads();
    if (t == 0) {
        float s = 0.f;
        for (int kk = 0; kk < TOPK; kk++) s += fin_e[kk];
        s_sum = 1.0f / s;
    }
    __syncthreads();
    if (t < TOPK) {
        g_tidx[b * TOPK + t] = fin_idx[t];
        g_tw[b * TOPK + t]   = fin_e[t] * s_sum;
    }
}

// ---------------- 3) weighted block gather + blend (l-major, MLP batched) ----
__global__ __launch_bounds__(128) void gather_kernel(const float* __restrict__ enc,
                                                     const float* __restrict__ fp,
                                                     const float* __restrict__ weight,
                                                     float* __restrict__ out) {
    __shared__ const float4* s_p[TOPK];
    __shared__ float s_w[TOPK];
    int b = blockIdx.x & (NB - 1);     // fast dim: batch -> concurrent CTAs share l
    int l = blockIdx.x >> 7;           // slow dim: row within block
    int t = threadIdx.x;               // 128 threads x float4 = 512 floats
    if (t < TOPK) {
        s_p[t] = (const float4*)(fp + ((size_t)g_tidx[b * TOPK + t] * BLKR + l) * D);
        s_w[t] = g_tw[b * TOPK + t];
    }
    __syncthreads();

    float ax = 0.f, ay = 0.f, az = 0.f, aw = 0.f;
#pragma unroll
    for (int kk = 0; kk < TOPK; kk += 10) {
        float4 v[10];
#pragma unroll
        for (int u = 0; u < 10; u++) v[u] = s_p[kk + u][t];
#pragma unroll
        for (int u = 0; u < 10; u++) {
            float w = s_w[kk + u];
            ax += w * v[u].x; ay += w * v[u].y; az += w * v[u].z; aw += w * v[u].w;
        }
    }

    float wm = weight[0];
    float em = 1.f - wm;
    size_t off = ((size_t)b * BLKR + l) * D;
    float4 e = ((const float4*)(enc + off))[t];
    float4 o;
    o.x = ax * wm + e.x * em;
    o.y = ay * wm + e.y * em;
    o.z = az * wm + e.z * em;
    o.w = aw * wm + e.w * em;
    ((float4*)(out + off))[t] = o;
}

// ---------------- launch ----------------
extern "C" void kernel_launch(void* const* d_in, const int* in_sizes, int n_in,
                              void* d_out, int out_size) {
    const float* enc = (const float*)d_in[0];   // [128, 64, 512]
    const float* q   = (const float*)d_in[1];   // [128, 512]
    const float* mc  = (const float*)d_in[2];   // [6304, 512]
    const float* fp  = (const float*)d_in[3];   // [403456, 512]
    const float* w   = (const float*)d_in[4];   // [1]
    float* out = (float*)d_out;                 // [128, 64, 512]

    cos_gemm_kernel<<<dim3(M / GBN, KSPLIT), 256>>>(q, mc);
    topk_kernel<<<NB, 256>>>(q);
    gather_kernel<<<NB * BLKR, 128>>>(enc, fp, w, out);
}